// round 14
// baseline (speedup 1.0000x reference)
#include <cuda_runtime.h>
#include <cuda_fp16.h>
#include <cstdint>

// out[784,65536] = relu( bcirc(W)[784,784] @ x[784,65536] + bias )
// mma.sync.m16n8k16.f16 (fp32 accum). 4 warps (2m x 2n), 128 threads, 2 CTAs/SM,
// 3-stage cp.async pipeline. K exact: 12 BK=64 chunks + peeled 16-k tail.
// M exact, fused: grid(7,512); bx<6 -> MT=4 tile (rows bx*128..), bx==6 -> MT=1
// thin tile (rows 768..799). Thin CTAs co-schedule with full CTAs (one kernel).
// A: half bcirc(W), XOR swizzle, ldmatrix.x4.
// B: x pre-converted to half; k-major [64][136] smem; ldmatrix.x4.trans.

#define BATCH   65536
#define K_PAD   832
#define BK      64
#define NFULL   12                       // full chunks (k 0..767); tail = chunk 12
#define NSTAGE  3

#define A_BUF    16384                   // 128 rows x 128 B (64 half per row)
#define B_STRH   136                     // halfs per k-row (128 + 8 pad) = 272 B
#define B_BUF    (BK * B_STRH * 2)       // 17408
#define STAGE    (A_BUF + B_BUF)         // 33792
#define SMEM_TOTAL (NSTAGE * STAGE)      // 101376

__device__ __align__(16) __half g_Ah[896 * K_PAD];           // bcirc(W) half
__device__ __align__(16) __half g_xh[784ULL * BATCH];        // x in half (103 MB)

// ---------------- helpers ----------------
__device__ __forceinline__ uint32_t smem_u32(const void* p) {
    uint32_t a;
    asm("{ .reg .u64 t; cvta.to.shared.u64 t, %1; cvt.u32.u64 %0, t; }" : "=r"(a) : "l"(p));
    return a;
}
__device__ __forceinline__ void cp_async16(uint32_t dst, const void* src) {
    asm volatile("cp.async.cg.shared.global [%0], [%1], 16;" :: "r"(dst), "l"(src));
}
__device__ __forceinline__ void cp_async16_zfill(uint32_t dst, const void* src, bool pred) {
    int sz = pred ? 16 : 0;
    asm volatile("cp.async.cg.shared.global [%0], [%1], 16, %2;"
                 :: "r"(dst), "l"(src), "r"(sz));
}
__device__ __forceinline__ void cp_commit() {
    asm volatile("cp.async.commit_group;" ::: "memory");
}
__device__ __forceinline__ void ldsm_x4(uint32_t& r0, uint32_t& r1, uint32_t& r2,
                                        uint32_t& r3, uint32_t addr) {
    asm volatile("ldmatrix.sync.aligned.m8n8.x4.shared.b16 {%0,%1,%2,%3}, [%4];"
                 : "=r"(r0), "=r"(r1), "=r"(r2), "=r"(r3) : "r"(addr));
}
__device__ __forceinline__ void ldsm_x4_trans(uint32_t& r0, uint32_t& r1, uint32_t& r2,
                                              uint32_t& r3, uint32_t addr) {
    asm volatile("ldmatrix.sync.aligned.m8n8.x4.trans.shared.b16 {%0,%1,%2,%3}, [%4];"
                 : "=r"(r0), "=r"(r1), "=r"(r2), "=r"(r3) : "r"(addr));
}
__device__ __forceinline__ void mma_f16(float* c, const uint32_t* a, const uint32_t* b) {
    asm volatile(
        "mma.sync.aligned.m16n8k16.row.col.f32.f16.f16.f32 "
        "{%0,%1,%2,%3}, {%4,%5,%6,%7}, {%8,%9}, {%0,%1,%2,%3};"
        : "+f"(c[0]), "+f"(c[1]), "+f"(c[2]), "+f"(c[3])
        : "r"(a[0]), "r"(a[1]), "r"(a[2]), "r"(a[3]), "r"(b[0]), "r"(b[1]));
}

// ---------------- merged prep: build A (first NA blocks) + convert x ----------------
#define NA_BLOCKS ((896 * K_PAD + 255) / 256)
#define NX_BLOCKS ((784 * BATCH / 8) / 256)

__global__ void prep_kernel(const float* __restrict__ W, const float* __restrict__ x) {
    if (blockIdx.x < NA_BLOCKS) {
        int idx = blockIdx.x * 256 + threadIdx.x;
        if (idx >= 896 * K_PAD) return;
        int r = idx / K_PAD, k = idx - r * K_PAD;
        float v = 0.0f;
        if (r < 784 && k < 784) {
            int ko = r / 28, m = r % 28, j = k / 28, n = k % 28;
            int l = ko - j; if (l < 0) l += 28;
            v = W[l * 784 + m * 28 + n];
        }
        g_Ah[idx] = __float2half_rn(v);
    } else {
        size_t i = ((size_t)(blockIdx.x - NA_BLOCKS) * 256 + threadIdx.x) * 8;
        float4 v0 = __ldg((const float4*)(x + i));
        float4 v1 = __ldg((const float4*)(x + i + 4));
        __half2* dst = (__half2*)(g_xh + i);
        dst[0] = __floats2half2_rn(v0.x, v0.y);
        dst[1] = __floats2half2_rn(v0.z, v0.w);
        dst[2] = __floats2half2_rn(v1.x, v1.y);
        dst[3] = __floats2half2_rn(v1.z, v1.w);
    }
}

// ---------------- GEMM body: 4 warps, MT m16-fragments per warp_m ----------------
template<int MT>
__device__ __forceinline__ void gemm_body(float* __restrict__ out,
                                          const float* __restrict__ bias,
                                          char* smem, int bm0, int bn0) {
    const uint32_t sb = smem_u32(smem);

    const int tid    = threadIdx.x;
    const int lane   = tid & 31;
    const int wid    = tid >> 5;
    const int warp_m = wid & 1;          // row halves 0 / 16*MT
    const int warp_n = wid >> 1;         // cols 0 / 64

    // producer: one full stage (A (32*MT)x64 half + B 64x128 half), one commit
    auto issue_stage = [&](int c, int s) {
        const uint32_t ab = sb + s * STAGE;
        const uint32_t bb = ab + A_BUF;
        const __half* asrc = g_Ah + (size_t)bm0 * K_PAD + c * BK;
        #pragma unroll
        for (int i = 0; i < 2 * MT; ++i) {            // A
            int idx = i * 128 + tid;
            int row = idx >> 3, kc = idx & 7;
            int chunk = kc ^ (row & 7);
            cp_async16(ab + row * 128 + chunk * 16,
                       asrc + (size_t)row * K_PAD + kc * 8);
        }
        #pragma unroll
        for (int i = 0; i < 8; ++i) {                 // B
            int idx  = i * 128 + tid;
            int krow = idx >> 4, c16 = idx & 15;
            int kg   = c * BK + krow;
            cp_async16_zfill(bb + krow * (B_STRH * 2) + c16 * 16,
                             g_xh + (size_t)kg * BATCH + bn0 + c16 * 8, kg < 784);
        }
        cp_commit();
    };
    // tail producer: chunk 12 = k 768..783 (16 rows), statically slot 0
    auto issue_tail = [&]() {
        const uint32_t ab = sb;                       // slot 0 (12 % 3)
        const uint32_t bb = ab + A_BUF;
        const __half* asrc = g_Ah + (size_t)bm0 * K_PAD + NFULL * BK;
        #pragma unroll
        for (int i = 0; i < 2 * MT; ++i) {            // A: only kc 0,1 real
            int idx = i * 128 + tid;
            int row = idx >> 3, kc = idx & 7;
            int chunk = kc ^ (row & 7);
            cp_async16_zfill(ab + row * 128 + chunk * 16,
                             asrc + (size_t)row * K_PAD + kc * 8, kc < 2);
        }
        #pragma unroll
        for (int i = 0; i < 8; ++i) {                 // B: rows 0..15 real
            int idx  = i * 128 + tid;
            int krow = idx >> 4, c16 = idx & 15;
            cp_async16_zfill(bb + krow * (B_STRH * 2) + c16 * 16,
                             g_xh + (size_t)(NFULL * BK + krow) * BATCH + bn0 + c16 * 8,
                             krow < 16);
        }
        cp_commit();
    };

    float acc[MT][8][4];
    #pragma unroll
    for (int mt = 0; mt < MT; ++mt)
        #pragma unroll
        for (int nt = 0; nt < 8; ++nt)
            #pragma unroll
            for (int q = 0; q < 4; ++q) acc[mt][nt][q] = 0.0f;

    issue_stage(0, 0);
    issue_stage(1, 1);

    // A ldmatrix lane mapping
    const int m8     = lane >> 3;
    const int rowoff = (lane & 7) + (m8 & 1) * 8;
    const int kcsel  = m8 >> 1;
    // B ldmatrix.trans lane mapping
    const int bq  = lane >> 3;
    const int b_krow_off = (bq & 1) * 8 + (lane & 7);
    const int b_n_off    = (bq >> 1) * 8;

    for (int c = 0; c < NFULL; ++c) {
        asm volatile("cp.async.wait_group 1;" ::: "memory");
        __syncthreads();

        if (c < NFULL - 2)       issue_stage(c + 2, (c + 2) % NSTAGE);
        else if (c == NFULL - 2) issue_tail();

        const uint32_t ab = sb + (c % NSTAGE) * STAGE;
        const uint32_t bb = ab + A_BUF;

        #pragma unroll
        for (int ks = 0; ks < 4; ++ks) {             // 4 k-steps of 16
            uint32_t af[MT][4];
            #pragma unroll
            for (int mt = 0; mt < MT; ++mt) {
                int row = warp_m * (16 * MT) + mt * 16 + rowoff;
                int kc  = ks * 2 + kcsel;
                int chunk = kc ^ (row & 7);
                ldsm_x4(af[mt][0], af[mt][1], af[mt][2], af[mt][3],
                        ab + row * 128 + chunk * 16);
            }
            uint32_t bf[8][2];
            #pragma unroll
            for (int p = 0; p < 4; ++p) {            // 4 x 16-wide n sub-tiles
                int k = ks * 16 + b_krow_off;
                int n = warp_n * 64 + p * 16 + b_n_off;
                uint32_t r0, r1, r2, r3;
                ldsm_x4_trans(r0, r1, r2, r3, bb + (k * B_STRH + n) * 2);
                bf[2 * p][0] = r0;     bf[2 * p][1] = r1;
                bf[2 * p + 1][0] = r2; bf[2 * p + 1][1] = r3;
            }
            #pragma unroll
            for (int nt = 0; nt < 8; ++nt)
                #pragma unroll
                for (int mt = 0; mt < MT; ++mt)
                    mma_f16(acc[mt][nt], af[mt], bf[nt]);
        }
    }

    // ---- peeled tail chunk: k 768..783, one k-step (ks = 0), slot 0 ----
    asm volatile("cp.async.wait_group 0;" ::: "memory");
    __syncthreads();
    {
        const uint32_t ab = sb;                       // slot 0
        const uint32_t bb = ab + A_BUF;
        uint32_t af[MT][4];
        #pragma unroll
        for (int mt = 0; mt < MT; ++mt) {
            int row = warp_m * (16 * MT) + mt * 16 + rowoff;
            int chunk = kcsel ^ (row & 7);            // ks = 0
            ldsm_x4(af[mt][0], af[mt][1], af[mt][2], af[mt][3],
                    ab + row * 128 + chunk * 16);
        }
        uint32_t bf[8][2];
        #pragma unroll
        for (int p = 0; p < 4; ++p) {
            int k = b_krow_off;                       // ks = 0
            int n = warp_n * 64 + p * 16 + b_n_off;
            uint32_t r0, r1, r2, r3;
            ldsm_x4_trans(r0, r1, r2, r3, bb + (k * B_STRH + n) * 2);
            bf[2 * p][0] = r0;     bf[2 * p][1] = r1;
            bf[2 * p + 1][0] = r2; bf[2 * p + 1][1] = r3;
        }
        #pragma unroll
        for (int nt = 0; nt < 8; ++nt)
            #pragma unroll
            for (int mt = 0; mt < MT; ++mt)
                mma_f16(acc[mt][nt], af[mt], bf[nt]);
    }

    // ---- epilogue: bias + relu + STG.64 ----
    #pragma unroll
    for (int mt = 0; mt < MT; ++mt) {
        int m0 = bm0 + warp_m * (16 * MT) + mt * 16 + (lane >> 2);
        int m1 = m0 + 8;
        float b0 = (m0 < 784) ? __ldg(bias + m0) : 0.0f;
        float b1 = (m1 < 784) ? __ldg(bias + m1) : 0.0f;
        #pragma unroll
        for (int nt = 0; nt < 8; ++nt) {
            int n = bn0 + warp_n * 64 + nt * 8 + (lane & 3) * 2;
            if (m0 < 784) {
                float2 v;
                v.x = fmaxf(acc[mt][nt][0] + b0, 0.0f);
                v.y = fmaxf(acc[mt][nt][1] + b0, 0.0f);
                *reinterpret_cast<float2*>(out + (size_t)m0 * BATCH + n) = v;
            }
            if (m1 < 784) {
                float2 v;
                v.x = fmaxf(acc[mt][nt][2] + b1, 0.0f);
                v.y = fmaxf(acc[mt][nt][3] + b1, 0.0f);
                *reinterpret_cast<float2*>(out + (size_t)m1 * BATCH + n) = v;
            }
        }
    }
}

// ---------------- fused kernel: full tiles (bx<6) + thin tile (bx==6) ----------------
__global__ void __launch_bounds__(128, 2)
tnn_gemm_kernel(float* __restrict__ out, const float* __restrict__ bias) {
    extern __shared__ char smem[];
    const int bn0 = blockIdx.y * 128;
    if (blockIdx.x < 6) {
        gemm_body<4>(out, bias, smem, blockIdx.x * 128, bn0);
    } else {
        gemm_body<1>(out, bias, smem, 768, bn0);
    }
}

// ---------------- launch ----------------
extern "C" void kernel_launch(void* const* d_in, const int* in_sizes, int n_in,
                              void* d_out, int out_size) {
    const float *x = nullptr, *W = nullptr, *B = nullptr;
    for (int i = 0; i < n_in; ++i) {
        if (in_sizes[i] > 1000000)      x = (const float*)d_in[i];
        else if (in_sizes[i] == 21952)  W = (const float*)d_in[i];
        else                            B = (const float*)d_in[i];
    }
    cudaFuncSetAttribute(tnn_gemm_kernel,
                         cudaFuncAttributeMaxDynamicSharedMemorySize, SMEM_TOTAL);
    prep_kernel<<<NA_BLOCKS + NX_BLOCKS, 256>>>(W, x);
    dim3 grid(7, BATCH / 128);
    tnn_gemm_kernel<<<grid, 128, SMEM_TOTAL>>>((float*)d_out, B);
}

// round 15
// speedup vs baseline: 1.4401x; 1.4401x over previous
#include <cuda_runtime.h>
#include <cuda_fp16.h>
#include <cstdint>

// out[784,65536] = relu( bcirc(W)[784,784] @ x[784,65536] + bias )
// mma.sync.m16n8k16.f16 (fp32 accum). 4 warps (2m x 2n), 128 threads, 2 CTAs/SM,
// 3-stage cp.async pipeline. K exact: 12 BK=64 chunks + peeled 16-k tail.
// M exact: TWO specialized kernels (R13 codegen): MT=4 grid(6,512) rows 0..767,
// MT=1 grid(1,512) rows 768..799 -- run CONCURRENTLY via stream fork/join
// (events) inside graph capture, so thin CTAs fill the full kernel's tail waves.
// A: half bcirc(W), XOR swizzle, ldmatrix.x4.
// B: x pre-converted to half; k-major [64][136] smem; ldmatrix.x4.trans.

#define BATCH   65536
#define K_PAD   832
#define BK      64
#define NFULL   12                       // full chunks (k 0..767); tail = chunk 12
#define NSTAGE  3

#define A_BUF    16384                   // 128 rows x 128 B (64 half per row)
#define B_STRH   136                     // halfs per k-row (128 + 8 pad) = 272 B
#define B_BUF    (BK * B_STRH * 2)       // 17408
#define STAGE    (A_BUF + B_BUF)         // 33792
#define SMEM_TOTAL (NSTAGE * STAGE)      // 101376

__device__ __align__(16) __half g_Ah[896 * K_PAD];           // bcirc(W) half
__device__ __align__(16) __half g_xh[784ULL * BATCH];        // x in half (103 MB)

// ---------------- helpers ----------------
__device__ __forceinline__ uint32_t smem_u32(const void* p) {
    uint32_t a;
    asm("{ .reg .u64 t; cvta.to.shared.u64 t, %1; cvt.u32.u64 %0, t; }" : "=r"(a) : "l"(p));
    return a;
}
__device__ __forceinline__ void cp_async16(uint32_t dst, const void* src) {
    asm volatile("cp.async.cg.shared.global [%0], [%1], 16;" :: "r"(dst), "l"(src));
}
__device__ __forceinline__ void cp_async16_zfill(uint32_t dst, const void* src, bool pred) {
    int sz = pred ? 16 : 0;
    asm volatile("cp.async.cg.shared.global [%0], [%1], 16, %2;"
                 :: "r"(dst), "l"(src), "r"(sz));
}
__device__ __forceinline__ void cp_commit() {
    asm volatile("cp.async.commit_group;" ::: "memory");
}
__device__ __forceinline__ void ldsm_x4(uint32_t& r0, uint32_t& r1, uint32_t& r2,
                                        uint32_t& r3, uint32_t addr) {
    asm volatile("ldmatrix.sync.aligned.m8n8.x4.shared.b16 {%0,%1,%2,%3}, [%4];"
                 : "=r"(r0), "=r"(r1), "=r"(r2), "=r"(r3) : "r"(addr));
}
__device__ __forceinline__ void ldsm_x4_trans(uint32_t& r0, uint32_t& r1, uint32_t& r2,
                                              uint32_t& r3, uint32_t addr) {
    asm volatile("ldmatrix.sync.aligned.m8n8.x4.trans.shared.b16 {%0,%1,%2,%3}, [%4];"
                 : "=r"(r0), "=r"(r1), "=r"(r2), "=r"(r3) : "r"(addr));
}
__device__ __forceinline__ void mma_f16(float* c, const uint32_t* a, const uint32_t* b) {
    asm volatile(
        "mma.sync.aligned.m16n8k16.row.col.f32.f16.f16.f32 "
        "{%0,%1,%2,%3}, {%4,%5,%6,%7}, {%8,%9}, {%0,%1,%2,%3};"
        : "+f"(c[0]), "+f"(c[1]), "+f"(c[2]), "+f"(c[3])
        : "r"(a[0]), "r"(a[1]), "r"(a[2]), "r"(a[3]), "r"(b[0]), "r"(b[1]));
}

// ---------------- merged prep: build A (first NA blocks) + convert x ----------------
#define NA_BLOCKS ((896 * K_PAD + 255) / 256)
#define NX_BLOCKS ((784 * BATCH / 4) / 256)

__global__ void prep_kernel(const float* __restrict__ W, const float* __restrict__ x) {
    if (blockIdx.x < NA_BLOCKS) {
        int idx = blockIdx.x * 256 + threadIdx.x;
        if (idx >= 896 * K_PAD) return;
        int r = idx / K_PAD, k = idx - r * K_PAD;
        float v = 0.0f;
        if (r < 784 && k < 784) {
            int ko = r / 28, m = r % 28, j = k / 28, n = k % 28;
            int l = ko - j; if (l < 0) l += 28;
            v = W[l * 784 + m * 28 + n];
        }
        g_Ah[idx] = __float2half_rn(v);
    } else {
        size_t i = ((size_t)(blockIdx.x - NA_BLOCKS) * 256 + threadIdx.x) * 4;
        float4 v = __ldg((const float4*)(x + i));
        __half2* dst = (__half2*)(g_xh + i);
        dst[0] = __floats2half2_rn(v.x, v.y);
        dst[1] = __floats2half2_rn(v.z, v.w);
    }
}

// ---------------- main GEMM: 4 warps, MT m16-fragments per warp_m ----------------
template<int MT, int MBASE>
__global__ void __launch_bounds__(128, 2)
tnn_gemm_kernel(float* __restrict__ out, const float* __restrict__ bias) {
    extern __shared__ char smem[];
    const uint32_t sb = smem_u32(smem);

    const int tid    = threadIdx.x;
    const int lane   = tid & 31;
    const int wid    = tid >> 5;
    const int warp_m = wid & 1;          // row halves 0 / 16*MT
    const int warp_n = wid >> 1;         // cols 0 / 64
    const int bm0    = MBASE + blockIdx.x * 128;   // m base of this tile
    const int bn0    = blockIdx.y * 128;           // batch strip

    // producer: one full stage (A (32*MT)x64 half + B 64x128 half), one commit
    auto issue_stage = [&](int c, int s) {
        const uint32_t ab = sb + s * STAGE;
        const uint32_t bb = ab + A_BUF;
        const __half* asrc = g_Ah + (size_t)bm0 * K_PAD + c * BK;
        #pragma unroll
        for (int i = 0; i < 2 * MT; ++i) {            // A
            int idx = i * 128 + tid;
            int row = idx >> 3, kc = idx & 7;
            int chunk = kc ^ (row & 7);
            cp_async16(ab + row * 128 + chunk * 16,
                       asrc + (size_t)row * K_PAD + kc * 8);
        }
        #pragma unroll
        for (int i = 0; i < 8; ++i) {                 // B
            int idx  = i * 128 + tid;
            int krow = idx >> 4, c16 = idx & 15;
            int kg   = c * BK + krow;
            cp_async16_zfill(bb + krow * (B_STRH * 2) + c16 * 16,
                             g_xh + (size_t)kg * BATCH + bn0 + c16 * 8, kg < 784);
        }
        cp_commit();
    };
    // tail producer: chunk 12 = k 768..783 (16 rows), statically slot 0
    auto issue_tail = [&]() {
        const uint32_t ab = sb;                       // slot 0 (12 % 3)
        const uint32_t bb = ab + A_BUF;
        const __half* asrc = g_Ah + (size_t)bm0 * K_PAD + NFULL * BK;
        #pragma unroll
        for (int i = 0; i < 2 * MT; ++i) {            // A: only kc 0,1 real
            int idx = i * 128 + tid;
            int row = idx >> 3, kc = idx & 7;
            int chunk = kc ^ (row & 7);
            cp_async16_zfill(ab + row * 128 + chunk * 16,
                             asrc + (size_t)row * K_PAD + kc * 8, kc < 2);
        }
        #pragma unroll
        for (int i = 0; i < 8; ++i) {                 // B: rows 0..15 real
            int idx  = i * 128 + tid;
            int krow = idx >> 4, c16 = idx & 15;
            cp_async16_zfill(bb + krow * (B_STRH * 2) + c16 * 16,
                             g_xh + (size_t)(NFULL * BK + krow) * BATCH + bn0 + c16 * 8,
                             krow < 16);
        }
        cp_commit();
    };

    float acc[MT][8][4];
    #pragma unroll
    for (int mt = 0; mt < MT; ++mt)
        #pragma unroll
        for (int nt = 0; nt < 8; ++nt)
            #pragma unroll
            for (int q = 0; q < 4; ++q) acc[mt][nt][q] = 0.0f;

    issue_stage(0, 0);
    issue_stage(1, 1);

    // A ldmatrix lane mapping
    const int m8     = lane >> 3;
    const int rowoff = (lane & 7) + (m8 & 1) * 8;
    const int kcsel  = m8 >> 1;
    // B ldmatrix.trans lane mapping
    const int bq  = lane >> 3;
    const int b_krow_off = (bq & 1) * 8 + (lane & 7);
    const int b_n_off    = (bq >> 1) * 8;

    for (int c = 0; c < NFULL; ++c) {
        asm volatile("cp.async.wait_group 1;" ::: "memory");
        __syncthreads();

        if (c < NFULL - 2)       issue_stage(c + 2, (c + 2) % NSTAGE);
        else if (c == NFULL - 2) issue_tail();

        const uint32_t ab = sb + (c % NSTAGE) * STAGE;
        const uint32_t bb = ab + A_BUF;

        #pragma unroll
        for (int ks = 0; ks < 4; ++ks) {             // 4 k-steps of 16
            uint32_t af[MT][4];
            #pragma unroll
            for (int mt = 0; mt < MT; ++mt) {
                int row = warp_m * (16 * MT) + mt * 16 + rowoff;
                int kc  = ks * 2 + kcsel;
                int chunk = kc ^ (row & 7);
                ldsm_x4(af[mt][0], af[mt][1], af[mt][2], af[mt][3],
                        ab + row * 128 + chunk * 16);
            }
            uint32_t bf[8][2];
            #pragma unroll
            for (int p = 0; p < 4; ++p) {            // 4 x 16-wide n sub-tiles
                int k = ks * 16 + b_krow_off;
                int n = warp_n * 64 + p * 16 + b_n_off;
                uint32_t r0, r1, r2, r3;
                ldsm_x4_trans(r0, r1, r2, r3, bb + (k * B_STRH + n) * 2);
                bf[2 * p][0] = r0;     bf[2 * p][1] = r1;
                bf[2 * p + 1][0] = r2; bf[2 * p + 1][1] = r3;
            }
            #pragma unroll
            for (int nt = 0; nt < 8; ++nt)
                #pragma unroll
                for (int mt = 0; mt < MT; ++mt)
                    mma_f16(acc[mt][nt], af[mt], bf[nt]);
        }
    }

    // ---- peeled tail chunk: k 768..783, one k-step (ks = 0), slot 0 ----
    asm volatile("cp.async.wait_group 0;" ::: "memory");
    __syncthreads();
    {
        const uint32_t ab = sb;                       // slot 0
        const uint32_t bb = ab + A_BUF;
        uint32_t af[MT][4];
        #pragma unroll
        for (int mt = 0; mt < MT; ++mt) {
            int row = warp_m * (16 * MT) + mt * 16 + rowoff;
            int chunk = kcsel ^ (row & 7);            // ks = 0
            ldsm_x4(af[mt][0], af[mt][1], af[mt][2], af[mt][3],
                    ab + row * 128 + chunk * 16);
        }
        uint32_t bf[8][2];
        #pragma unroll
        for (int p = 0; p < 4; ++p) {
            int k = b_krow_off;                       // ks = 0
            int n = warp_n * 64 + p * 16 + b_n_off;
            uint32_t r0, r1, r2, r3;
            ldsm_x4_trans(r0, r1, r2, r3, bb + (k * B_STRH + n) * 2);
            bf[2 * p][0] = r0;     bf[2 * p][1] = r1;
            bf[2 * p + 1][0] = r2; bf[2 * p + 1][1] = r3;
        }
        #pragma unroll
        for (int nt = 0; nt < 8; ++nt)
            #pragma unroll
            for (int mt = 0; mt < MT; ++mt)
                mma_f16(acc[mt][nt], af[mt], bf[nt]);
    }

    // ---- epilogue: bias + relu + STG.64 ----
    #pragma unroll
    for (int mt = 0; mt < MT; ++mt) {
        int m0 = bm0 + warp_m * (16 * MT) + mt * 16 + (lane >> 2);
        int m1 = m0 + 8;
        float b0 = (m0 < 784) ? __ldg(bias + m0) : 0.0f;
        float b1 = (m1 < 784) ? __ldg(bias + m1) : 0.0f;
        #pragma unroll
        for (int nt = 0; nt < 8; ++nt) {
            int n = bn0 + warp_n * 64 + nt * 8 + (lane & 3) * 2;
            if (m0 < 784) {
                float2 v;
                v.x = fmaxf(acc[mt][nt][0] + b0, 0.0f);
                v.y = fmaxf(acc[mt][nt][1] + b0, 0.0f);
                *reinterpret_cast<float2*>(out + (size_t)m0 * BATCH + n) = v;
            }
            if (m1 < 784) {
                float2 v;
                v.x = fmaxf(acc[mt][nt][2] + b1, 0.0f);
                v.y = fmaxf(acc[mt][nt][3] + b1, 0.0f);
                *reinterpret_cast<float2*>(out + (size_t)m1 * BATCH + n) = v;
            }
        }
    }
}

// ---------------- launch: prep -> fork(thin || full) -> join ----------------
extern "C" void kernel_launch(void* const* d_in, const int* in_sizes, int n_in,
                              void* d_out, int out_size) {
    const float *x = nullptr, *W = nullptr, *B = nullptr;
    for (int i = 0; i < n_in; ++i) {
        if (in_sizes[i] > 1000000)      x = (const float*)d_in[i];
        else if (in_sizes[i] == 21952)  W = (const float*)d_in[i];
        else                            B = (const float*)d_in[i];
    }
    static int inited = 0;
    static cudaStream_t s2;
    static cudaEvent_t evA, evB;
    if (!inited) {
        cudaFuncSetAttribute(tnn_gemm_kernel<4, 0>,
                             cudaFuncAttributeMaxDynamicSharedMemorySize, SMEM_TOTAL);
        cudaFuncSetAttribute(tnn_gemm_kernel<1, 768>,
                             cudaFuncAttributeMaxDynamicSharedMemorySize, SMEM_TOTAL);
        cudaStreamCreateWithFlags(&s2, cudaStreamNonBlocking);
        cudaEventCreateWithFlags(&evA, cudaEventDisableTiming);
        cudaEventCreateWithFlags(&evB, cudaEventDisableTiming);
        inited = 1;
    }

    prep_kernel<<<NA_BLOCKS + NX_BLOCKS, 256>>>(W, x);

    // fork: thin kernel on s2 runs concurrently with full kernel on stream 0
    cudaEventRecord(evA, 0);
    cudaStreamWaitEvent(s2, evA, 0);
    dim3 grid_thin(1, BATCH / 128);
    tnn_gemm_kernel<1, 768><<<grid_thin, 128, SMEM_TOTAL, s2>>>((float*)d_out, B);
    dim3 grid_full(6, BATCH / 128);
    tnn_gemm_kernel<4, 0><<<grid_full, 128, SMEM_TOTAL>>>((float*)d_out, B);
    // join
    cudaEventRecord(evB, s2);
    cudaStreamWaitEvent(0, evB, 0);
}